// round 10
// baseline (speedup 1.0000x reference)
#include <cuda_runtime.h>
#include <cstdint>
#include <cstddef>

#define NB 16
#define NP 4096
#define NS 1024
#define NK 16
#define NKC 24
#define NF 256
#define NO 512
#define NPTS (NB*NP)
#define NQ   (NB*NS)
#define SEG  4
#define PSEG (NP/SEG)

#define POS_INF __int_as_float(0x7f800000)
#define NEG_INF __int_as_float(0xff800000)

typedef unsigned long long u64;

__device__ float    g_h[(size_t)NPTS * NO];
__device__ float    g_hn[NPTS];
__device__ int      g_fps[NQ];
__device__ float    g_part[2 * 128 * NO];
__device__ float    g_a[NO];
__device__ float    g_c[NO];
__device__ uint32_t g_q8[(size_t)NPTS * 64];   // packed int8 features (64 u32/point)
__device__ float    g_qs[NPTS];                // per-point quant scale
__device__ int      g_knni[(size_t)NQ * SEG * NKC];
__device__ int      g_nn[(size_t)NQ * NK];

// ---------------- f32x2 helpers (each half rounds exactly like scalar FFMA) --
__device__ __forceinline__ u64 dup2(float x) {
    u64 r;
    uint32_t b = __float_as_uint(x);
    asm("mov.b64 %0, {%1, %1};" : "=l"(r) : "r"(b));
    return r;
}
#define FMA2(acc, a, b) \
    asm("fma.rn.f32x2 %0, %1, %2, %0;" : "+l"(acc) : "l"(a), "l"(b))
__device__ __forceinline__ float2 unpack2(u64 v) {
    float2 r;
    asm("mov.b64 {%0, %1}, %2;" : "=f"(r.x), "=f"(r.y) : "l"(v));
    return r;
}

// ===================== K1: fused FPS + MLP-GEMM + xnorm (R7-proven) ==========
#define FPS_SMEM_BYTES ((NP * 3 + NS + 8 + 8 + 1) * 4)
#define GEMM_SMEM_BYTES (2 * 2 * 8 * 128 * 4)
#define FUSED_SMEM (FPS_SMEM_BYTES > GEMM_SMEM_BYTES ? FPS_SMEM_BYTES : GEMM_SMEM_BYTES)

__device__ void fps_body(char* smc, const float* __restrict__ positions,
                         const int* __restrict__ batch,
                         float* __restrict__ out_pos, float* __restrict__ out_batch,
                         int cloud) {
    float* spos  = (float*)smc;
    int*   sel   = (int*)(spos + NP * 3);
    float* rv    = (float*)(sel + NS);
    int*   ri    = (int*)(rv + 8);
    int*   slast = ri + 8;
    const int tid = threadIdx.x;
    const float* pos = positions + (size_t)cloud * NP * 3;
    for (int i = tid; i < NP * 3; i += 256) spos[i] = pos[i];
    __syncthreads();

    float px[16], py[16], pz[16], md[16];
#pragma unroll
    for (int j = 0; j < 16; j++) {
        int pt = tid + j * 256;
        px[j] = spos[pt * 3]; py[j] = spos[pt * 3 + 1]; pz[j] = spos[pt * 3 + 2];
        md[j] = POS_INF;
    }
    if (tid == 0) sel[0] = 0;
    int last = 0;
    const int lane = tid & 31, warp = tid >> 5;
    for (int it = 1; it < NS; it++) {
        float lx = spos[last * 3], ly = spos[last * 3 + 1], lz = spos[last * 3 + 2];
        float bv = NEG_INF; int bi = 0x7fffffff;
#pragma unroll
        for (int j = 0; j < 16; j++) {
            float dx = px[j] - lx, dy = py[j] - ly, dz = pz[j] - lz;
            float d = __fadd_rn(__fadd_rn(__fmul_rn(dx, dx), __fmul_rn(dy, dy)),
                                __fmul_rn(dz, dz));
            float m = fminf(md[j], d);
            md[j] = m;
            if (m > bv) { bv = m; bi = tid + j * 256; }
        }
#pragma unroll
        for (int off = 16; off > 0; off >>= 1) {
            float ov = __shfl_down_sync(0xffffffffu, bv, off);
            int   oi = __shfl_down_sync(0xffffffffu, bi, off);
            if (ov > bv || (ov == bv && oi < bi)) { bv = ov; bi = oi; }
        }
        if (lane == 0) { rv[warp] = bv; ri[warp] = bi; }
        __syncthreads();
        if (warp == 0) {
            float v = (lane < 8) ? rv[lane] : NEG_INF;
            int b = (lane < 8) ? ri[lane] : 0x7fffffff;
#pragma unroll
            for (int off = 4; off > 0; off >>= 1) {
                float ov = __shfl_down_sync(0xffffffffu, v, off);
                int   oi = __shfl_down_sync(0xffffffffu, b, off);
                if (ov > v || (ov == v && oi < b)) { v = ov; b = oi; }
            }
            if (lane == 0) { sel[it] = b; slast[0] = b; }
        }
        __syncthreads();
        last = slast[0];
    }
    for (int s = tid; s < NS; s += 256) {
        int loc = sel[s], g = cloud * NP + loc, oq = cloud * NS + s;
        g_fps[oq] = g;
        out_pos[oq * 3 + 0] = spos[loc * 3 + 0];
        out_pos[oq * 3 + 1] = spos[loc * 3 + 1];
        out_pos[oq * 3 + 2] = spos[loc * 3 + 2];
        out_batch[oq] = (float)batch[g];
    }
}

__global__ __launch_bounds__(256, 2) void fused_kernel(
    const float* __restrict__ A, const float* __restrict__ positions,
    const int* __restrict__ batch, const float* __restrict__ W,
    const float* __restrict__ bias,
    float* __restrict__ out_pos, float* __restrict__ out_batch) {
    extern __shared__ __align__(16) char smc[];
    if (blockIdx.x < 16) {
        fps_body(smc, positions, batch, out_pos, out_batch, blockIdx.x);
        return;
    }
    const int b = blockIdx.x - 16;
    const int bx = b & 3, by = b >> 2;
    float* As = (float*)smc;          // [2][8][128]
    float* Bs = As + 2 * 8 * 128;     // [2][8][128]
    const int tid = threadIdx.x;
    const int tx = tid & 15, ty = tid >> 4;
    const int arow = tid >> 1, half = tid & 1, acol = half * 4;
    const int brow = tid >> 5, bcol = (tid & 31) * 4;
    const float* aptr = A + (size_t)(by * 128 + arow) * NF + acol;
    const float* wbase = W + (size_t)brow * NO + bx * 128 + bcol;

    u64 acc2[8][4];
#pragma unroll
    for (int i = 0; i < 8; i++)
#pragma unroll
        for (int jp = 0; jp < 4; jp++) acc2[i][jp] = 0ull;
    float sq = 0.f;

    float4 av = *(const float4*)aptr;
    float4 bv = *(const float4*)wbase;
    for (int kb = 0; kb < 32; kb++) {
        float* Asb = As + (kb & 1) * 1024;
        float* Bsb = Bs + (kb & 1) * 1024;
        Asb[(acol + 0) * 128 + arow] = av.x;
        Asb[(acol + 1) * 128 + arow] = av.y;
        Asb[(acol + 2) * 128 + arow] = av.z;
        Asb[(acol + 3) * 128 + arow] = av.w;
        *(float4*)&Bsb[brow * 128 + bcol] = bv;
        if (bx == 0) {
            sq = fmaf(av.x, av.x, sq); sq = fmaf(av.y, av.y, sq);
            sq = fmaf(av.z, av.z, sq); sq = fmaf(av.w, av.w, sq);
        }
        __syncthreads();
        if (kb < 31) {
            av = *(const float4*)(aptr + (kb + 1) * 8);
            bv = *(const float4*)(wbase + (size_t)(kb + 1) * 8 * NO);
        }
#pragma unroll
        for (int k = 0; k < 8; k++) {
            float4 a0 = *(const float4*)&Asb[k * 128 + ty * 8];
            float4 a1 = *(const float4*)&Asb[k * 128 + ty * 8 + 4];
            const u64* bp = (const u64*)&Bsb[k * 128 + tx * 8];
            u64 b2[4] = {bp[0], bp[1], bp[2], bp[3]};
            u64 ad[8] = {dup2(a0.x), dup2(a0.y), dup2(a0.z), dup2(a0.w),
                         dup2(a1.x), dup2(a1.y), dup2(a1.z), dup2(a1.w)};
#pragma unroll
            for (int i = 0; i < 8; i++)
#pragma unroll
                for (int jp = 0; jp < 4; jp++)
                    FMA2(acc2[i][jp], ad[i], b2[jp]);
        }
    }

    if (bx == 0) {
        float o = __shfl_xor_sync(0xffffffffu, sq, 1);
        if (half == 0) g_hn[by * 128 + arow] = 0.5f * (sq + o);
    }

    const int ccol = bx * 128 + tx * 8;
    const int crow = by * 128 + ty * 8;
    float4 bb0 = *(const float4*)(bias + ccol);
    float4 bb1 = *(const float4*)(bias + ccol + 4);
#pragma unroll
    for (int i = 0; i < 8; i++) {
        float2 p0 = unpack2(acc2[i][0]), p1 = unpack2(acc2[i][1]);
        float2 p2 = unpack2(acc2[i][2]), p3 = unpack2(acc2[i][3]);
        float4 o0, o1;
        o0.x = p0.x + bb0.x; o0.y = p0.y + bb0.y;
        o0.z = p1.x + bb0.z; o0.w = p1.y + bb0.w;
        o1.x = p2.x + bb1.x; o1.y = p2.y + bb1.y;
        o1.z = p3.x + bb1.z; o1.w = p3.y + bb1.w;
        *(float4*)(g_h + (size_t)(crow + i) * NO + ccol) = o0;
        *(float4*)(g_h + (size_t)(crow + i) * NO + ccol + 4) = o1;
    }
}

// ===================== int8 quantization (1 warp per point) ==================
__global__ __launch_bounds__(256) void quant_kernel(const float* __restrict__ feat) {
    const int pt = blockIdx.x * 8 + (threadIdx.x >> 5);
    const int lane = threadIdx.x & 31;
    const float* f = feat + (size_t)pt * NF + lane * 8;
    float4 v0 = *(const float4*)f;
    float4 v1 = *(const float4*)(f + 4);
    float m = fmaxf(fmaxf(fmaxf(fabsf(v0.x), fabsf(v0.y)), fmaxf(fabsf(v0.z), fabsf(v0.w))),
                    fmaxf(fmaxf(fabsf(v1.x), fabsf(v1.y)), fmaxf(fabsf(v1.z), fabsf(v1.w))));
#pragma unroll
    for (int off = 16; off > 0; off >>= 1)
        m = fmaxf(m, __shfl_xor_sync(0xffffffffu, m, off));
    m = fmaxf(m, 1e-30f);
    float inv = 127.0f / m;
    int q[8];
    const float* vv0 = &v0.x;
    const float* vv1 = &v1.x;
#pragma unroll
    for (int j = 0; j < 4; j++) {
        q[j]     = max(-127, min(127, __float2int_rn(vv0[j] * inv)));
        q[j + 4] = max(-127, min(127, __float2int_rn(vv1[j] * inv)));
    }
    uint32_t p0 = (q[0] & 255) | ((q[1] & 255) << 8) | ((q[2] & 255) << 16) | ((uint32_t)(q[3] & 255) << 24);
    uint32_t p1 = (q[4] & 255) | ((q[5] & 255) << 8) | ((q[6] & 255) << 16) | ((uint32_t)(q[7] & 255) << 24);
    g_q8[(size_t)pt * 64 + lane * 2]     = p0;
    g_q8[(size_t)pt * 64 + lane * 2 + 1] = p1;
    if (lane == 0) g_qs[pt] = m * (1.0f / 127.0f);
}

// ===================== BN stats =====================
__global__ __launch_bounds__(512) void stats_partial_kernel() {
    int c = threadIdx.x, blk = blockIdx.x;
    float s = 0.f, s2 = 0.f;
    int r0 = blk * 512;
    for (int r = 0; r < 512; r++) {
        float v = g_h[(size_t)(r0 + r) * NO + c];
        s += v; s2 = fmaf(v, v, s2);
    }
    g_part[blk * NO + c] = s;
    g_part[128 * NO + blk * NO + c] = s2;
}
__global__ __launch_bounds__(512) void stats_final_kernel(const float* __restrict__ gamma,
                                                          const float* __restrict__ beta) {
    int c = threadIdx.x;
    float s = 0.f, s2 = 0.f;
    for (int b = 0; b < 128; b++) { s += g_part[b * NO + c]; s2 += g_part[128 * NO + b * NO + c]; }
    float inv = 1.0f / (float)NPTS;
    float mu = s * inv, var = s2 * inv - mu * mu;
    float a = gamma[c] * rsqrtf(var + 1e-5f);
    g_a[c] = a; g_c[c] = beta[c] - mu * a;
}

// ===================== KNN int8 candidate scorer (top-24 per segment) ========
// Whole-tile int8 GEMM: scores = sq*sx*dp4a_dot - hn (integer dot is exact).
#define I_Q  0                              // Q tile: 64 k x 128 rows (u32)
#define I_X  (I_Q + 64*128*4)               // X tile
#define I_SC (I_X + 64*128*4)               // int scores staged, 128 x 129
#define I_SX (I_SC + 128*129*4)             // x scales
#define I_HN (I_SX + 128*4)
#define I_TV (I_HN + 128*4)                 // 128 x 24 approx scores
#define I_TI (I_TV + 128*NKC*4)
#define KNN8_SMEM (I_TI + 128*NKC*4)        // 157184 B -> occ 1

__global__ __launch_bounds__(256, 1) void knn_i8_kernel() {
    extern __shared__ __align__(16) char smc[];
    uint32_t* Qs  = (uint32_t*)(smc + I_Q);
    uint32_t* Xs  = (uint32_t*)(smc + I_X);
    int*   Sc   = (int*)(smc + I_SC);
    float* sx_s = (float*)(smc + I_SX);
    float* hn_s = (float*)(smc + I_HN);
    float* topv = (float*)(smc + I_TV);
    int*   topi = (int*)(smc + I_TI);

    const int qt = blockIdx.x, sg = blockIdx.y, cloud = blockIdx.z;
    const int tid = threadIdx.x;
    const int tx = tid & 15, ty = tid >> 4;

    // load Q tile (gathered rows), transposed to k-major
    const int qbase = cloud * NS + qt * 128;
    for (int i = tid; i < 2048; i += 256) {      // 128 rows x 16 uint4
        int row = i & 127, kg = i >> 7;
        int qr = g_fps[qbase + row];
        uint4 v = ((const uint4*)(g_q8 + (size_t)qr * 64))[kg];
        Qs[(kg * 4 + 0) * 128 + row] = v.x;
        Qs[(kg * 4 + 1) * 128 + row] = v.y;
        Qs[(kg * 4 + 2) * 128 + row] = v.z;
        Qs[(kg * 4 + 3) * 128 + row] = v.w;
    }
    if (tid < 128) {
#pragma unroll
        for (int r = 0; r < NKC; r++) {
            topv[tid * NKC + r] = NEG_INF;
            topi[tid * NKC + r] = 0x7fffffff;
        }
    }
    // per-selection-thread query scale
    float sq_t = (tid < 128) ? g_qs[g_fps[qbase + tid]] : 0.f;
    const int xcloudbase = cloud * NP + sg * PSEG;
    __syncthreads();

    for (int t = 0; t < PSEG / 128; t++) {
        const int xbase = xcloudbase + t * 128;
        if (tid < 128) {
            sx_s[tid] = g_qs[xbase + tid];
            hn_s[tid] = g_hn[xbase + tid];
        }
        for (int i = tid; i < 2048; i += 256) {
            int row = i & 127, kg = i >> 7;
            uint4 v = ((const uint4*)(g_q8 + (size_t)(xbase + row) * 64))[kg];
            Xs[(kg * 4 + 0) * 128 + row] = v.x;
            Xs[(kg * 4 + 1) * 128 + row] = v.y;
            Xs[(kg * 4 + 2) * 128 + row] = v.z;
            Xs[(kg * 4 + 3) * 128 + row] = v.w;
        }
        __syncthreads();

        int acc[8][8];
#pragma unroll
        for (int i = 0; i < 8; i++)
#pragma unroll
            for (int j = 0; j < 8; j++) acc[i][j] = 0;

        for (int k = 0; k < 64; k++) {
            uint4 a0 = *(const uint4*)&Qs[k * 128 + ty * 8];
            uint4 a1 = *(const uint4*)&Qs[k * 128 + ty * 8 + 4];
            uint4 b0 = *(const uint4*)&Xs[k * 128 + tx * 8];
            uint4 b1 = *(const uint4*)&Xs[k * 128 + tx * 8 + 4];
            int ar[8] = {(int)a0.x, (int)a0.y, (int)a0.z, (int)a0.w,
                         (int)a1.x, (int)a1.y, (int)a1.z, (int)a1.w};
            int br[8] = {(int)b0.x, (int)b0.y, (int)b0.z, (int)b0.w,
                         (int)b1.x, (int)b1.y, (int)b1.z, (int)b1.w};
#pragma unroll
            for (int i = 0; i < 8; i++)
#pragma unroll
                for (int j = 0; j < 8; j++)
                    acc[i][j] = __dp4a(ar[i], br[j], acc[i][j]);
        }
        __syncthreads();   // Xs reads done before next tile overwrite (and Sc reuse)

#pragma unroll
        for (int i = 0; i < 8; i++)
#pragma unroll
            for (int j = 0; j < 8; j++)
                Sc[(ty * 8 + i) * 129 + tx * 8 + j] = acc[i][j];
        __syncthreads();

        if (tid < 128) {   // approx top-24, (score desc, idx asc)
            const int* scr = Sc + tid * 129;
            float* tv = topv + tid * NKC;
            int*   ti = topi + tid * NKC;
            float th = tv[NKC - 1];
            int  thi = ti[NKC - 1];
            for (int p = 0; p < 128; p++) {
                float s = sq_t * sx_s[p] * (float)scr[p] - hn_s[p];
                int gi = xbase + p;
                if (s > th || (s == th && gi < thi)) {
                    int r = NKC - 1;
                    while (r > 0) {
                        float pv = tv[r - 1];
                        int   pi = ti[r - 1];
                        if (s > pv || (s == pv && gi < pi)) {
                            tv[r] = pv; ti[r] = pi; r--;
                        } else break;
                    }
                    tv[r] = s; ti[r] = gi;
                    th = tv[NKC - 1]; thi = ti[NKC - 1];
                }
            }
        }
        __syncthreads();
    }

    if (tid < 128) {
        int q = qbase + tid;
#pragma unroll
        for (int r = 0; r < NKC; r++)
            g_knni[((size_t)q * SEG + sg) * NKC + r] = topi[tid * NKC + r];
    }
}

// ===================== exact rescore of 96 candidates -> top-16 ==============
// Bit-identical round-1 arithmetic: ascending-k fmaf dot, s -= 0.5|x|^2,
// ordering by (score desc, index asc).
__global__ __launch_bounds__(128) void rescore_kernel(const float* __restrict__ feat) {
    __shared__ float q[NF];
    __shared__ float sv[SEG * NKC];
    __shared__ int   si[SEG * NKC];
    const int qi = blockIdx.x, tid = threadIdx.x;
    const int qg = g_fps[qi];
    q[tid]       = feat[(size_t)qg * NF + tid];
    q[tid + 128] = feat[(size_t)qg * NF + 128 + tid];
    __syncthreads();

    if (tid < SEG * NKC) {
        int gi = g_knni[(size_t)qi * SEG * NKC + tid];
        const float4* x = (const float4*)(feat + (size_t)gi * NF);
        float s = 0.f;
#pragma unroll 8
        for (int k4 = 0; k4 < NF / 4; k4++) {
            float4 xv = x[k4];
            s = fmaf(q[k4 * 4 + 0], xv.x, s);
            s = fmaf(q[k4 * 4 + 1], xv.y, s);
            s = fmaf(q[k4 * 4 + 2], xv.z, s);
            s = fmaf(q[k4 * 4 + 3], xv.w, s);
        }
        s -= g_hn[gi];
        sv[tid] = s;
        si[tid] = gi;
    }
    __syncthreads();

    if (tid < SEG * NKC) {
        float s = sv[tid];
        int gi = si[tid];
        int cnt = 0;
        for (int j = 0; j < SEG * NKC; j++) {
            float vj = sv[j];
            cnt += (vj > s || (vj == s && si[j] < gi)) ? 1 : 0;
        }
        if (cnt < NK) g_nn[(size_t)qi * NK + cnt] = gi;
    }
}

// ===================== gather + max-pool + BN + ReLU =========================
__global__ __launch_bounds__(128) void gather_kernel(float* __restrict__ out) {
    __shared__ int nn[NK];
    const int q = blockIdx.x, tid = threadIdx.x;
    if (tid < NK) nn[tid] = g_nn[(size_t)q * NK + tid];
    __syncthreads();
    float mx[4] = {NEG_INF, NEG_INF, NEG_INF, NEG_INF};
    float mn[4] = {POS_INF, POS_INF, POS_INF, POS_INF};
#pragma unroll
    for (int n = 0; n < NK; n++) {
        const float* hp = g_h + (size_t)nn[n] * NO;
#pragma unroll
        for (int j = 0; j < 4; j++) {
            float v = hp[tid + j * 128];
            mx[j] = fmaxf(mx[j], v); mn[j] = fminf(mn[j], v);
        }
    }
    float* op = out + (size_t)q * NO;
#pragma unroll
    for (int j = 0; j < 4; j++) {
        int c = tid + j * 128;
        float a = g_a[c], cc = g_c[c];
        float o = fmaxf(fmaf(a, mx[j], cc), fmaf(a, mn[j], cc));
        op[c] = fmaxf(o, 0.0f);
    }
}

// ===================== launch =====================
extern "C" void kernel_launch(void* const* d_in, const int* in_sizes, int n_in,
                              void* d_out, int out_size) {
    (void)in_sizes; (void)n_in; (void)out_size;
    const float* features  = (const float*)d_in[0];
    const float* positions = (const float*)d_in[1];
    const int*   batch     = (const int*)d_in[2];
    const float* W         = (const float*)d_in[3];
    const float* bias      = (const float*)d_in[4];
    const float* gamma     = (const float*)d_in[5];
    const float* beta      = (const float*)d_in[6];

    float* out       = (float*)d_out;
    float* out_feat  = out;
    float* out_pos   = out + (size_t)NQ * NO;
    float* out_batch = out_pos + (size_t)NQ * 3;

    cudaFuncSetAttribute(fused_kernel, cudaFuncAttributeMaxDynamicSharedMemorySize, FUSED_SMEM);
    cudaFuncSetAttribute(knn_i8_kernel, cudaFuncAttributeMaxDynamicSharedMemorySize, KNN8_SMEM);

    quant_kernel<<<NPTS / 8, 256>>>(features);
    fused_kernel<<<16 + 2048, 256, FUSED_SMEM>>>(features, positions, batch, W, bias,
                                                 out_pos, out_batch);
    stats_partial_kernel<<<128, 512>>>();
    knn_i8_kernel<<<dim3(8, SEG, NB), 256, KNN8_SMEM>>>();   // 4th launch -> ncu
    stats_final_kernel<<<1, 512>>>(gamma, beta);
    rescore_kernel<<<NQ, 128>>>(features);
    gather_kernel<<<NQ, 128>>>(out_feat);
}

// round 11
// speedup vs baseline: 1.3447x; 1.3447x over previous
#include <cuda_runtime.h>
#include <cstdint>
#include <cstddef>

#define NB 16
#define NP 4096
#define NS 1024
#define NK 16
#define NKC 24
#define NF 256
#define NO 512
#define NPTS (NB*NP)
#define NQ   (NB*NS)
#define SEG  4
#define PSEG (NP/SEG)

#define POS_INF __int_as_float(0x7f800000)
#define NEG_INF __int_as_float(0xff800000)

typedef unsigned long long u64;

__device__ float    g_h[(size_t)NPTS * NO];
__device__ float    g_hn[NPTS];
__device__ int      g_fps[NQ];
__device__ float    g_part[2 * 128 * NO];
__device__ float    g_a[NO];
__device__ float    g_c[NO];
__device__ uint32_t g_q8[(size_t)NPTS * 64];   // packed int8 features (64 u32/point)
__device__ float    g_qs[NPTS];                // per-point quant scale
__device__ int      g_knni[(size_t)NQ * SEG * NKC];
__device__ int      g_nn[(size_t)NQ * NK];

// ---------------- f32x2 helpers (each half rounds exactly like scalar FFMA) --
__device__ __forceinline__ u64 dup2(float x) {
    u64 r;
    uint32_t b = __float_as_uint(x);
    asm("mov.b64 %0, {%1, %1};" : "=l"(r) : "r"(b));
    return r;
}
#define FMA2(acc, a, b) \
    asm("fma.rn.f32x2 %0, %1, %2, %0;" : "+l"(acc) : "l"(a), "l"(b))
__device__ __forceinline__ float2 unpack2(u64 v) {
    float2 r;
    asm("mov.b64 {%0, %1}, %2;" : "=f"(r.x), "=f"(r.y) : "l"(v));
    return r;
}

// ===================== K1: fused FPS + MLP-GEMM + xnorm (R7-proven) ==========
#define FPS_SMEM_BYTES ((NP * 3 + NS + 8 + 8 + 1) * 4)
#define GEMM_SMEM_BYTES (2 * 2 * 8 * 128 * 4)
#define FUSED_SMEM (FPS_SMEM_BYTES > GEMM_SMEM_BYTES ? FPS_SMEM_BYTES : GEMM_SMEM_BYTES)

__device__ void fps_body(char* smc, const float* __restrict__ positions,
                         const int* __restrict__ batch,
                         float* __restrict__ out_pos, float* __restrict__ out_batch,
                         int cloud) {
    float* spos  = (float*)smc;
    int*   sel   = (int*)(spos + NP * 3);
    float* rv    = (float*)(sel + NS);
    int*   ri    = (int*)(rv + 8);
    int*   slast = ri + 8;
    const int tid = threadIdx.x;
    const float* pos = positions + (size_t)cloud * NP * 3;
    for (int i = tid; i < NP * 3; i += 256) spos[i] = pos[i];
    __syncthreads();

    float px[16], py[16], pz[16], md[16];
#pragma unroll
    for (int j = 0; j < 16; j++) {
        int pt = tid + j * 256;
        px[j] = spos[pt * 3]; py[j] = spos[pt * 3 + 1]; pz[j] = spos[pt * 3 + 2];
        md[j] = POS_INF;
    }
    if (tid == 0) sel[0] = 0;
    int last = 0;
    const int lane = tid & 31, warp = tid >> 5;
    for (int it = 1; it < NS; it++) {
        float lx = spos[last * 3], ly = spos[last * 3 + 1], lz = spos[last * 3 + 2];
        float bv = NEG_INF; int bi = 0x7fffffff;
#pragma unroll
        for (int j = 0; j < 16; j++) {
            float dx = px[j] - lx, dy = py[j] - ly, dz = pz[j] - lz;
            float d = __fadd_rn(__fadd_rn(__fmul_rn(dx, dx), __fmul_rn(dy, dy)),
                                __fmul_rn(dz, dz));
            float m = fminf(md[j], d);
            md[j] = m;
            if (m > bv) { bv = m; bi = tid + j * 256; }
        }
#pragma unroll
        for (int off = 16; off > 0; off >>= 1) {
            float ov = __shfl_down_sync(0xffffffffu, bv, off);
            int   oi = __shfl_down_sync(0xffffffffu, bi, off);
            if (ov > bv || (ov == bv && oi < bi)) { bv = ov; bi = oi; }
        }
        if (lane == 0) { rv[warp] = bv; ri[warp] = bi; }
        __syncthreads();
        if (warp == 0) {
            float v = (lane < 8) ? rv[lane] : NEG_INF;
            int b = (lane < 8) ? ri[lane] : 0x7fffffff;
#pragma unroll
            for (int off = 4; off > 0; off >>= 1) {
                float ov = __shfl_down_sync(0xffffffffu, v, off);
                int   oi = __shfl_down_sync(0xffffffffu, b, off);
                if (ov > v || (ov == v && oi < b)) { v = ov; b = oi; }
            }
            if (lane == 0) { sel[it] = b; slast[0] = b; }
        }
        __syncthreads();
        last = slast[0];
    }
    for (int s = tid; s < NS; s += 256) {
        int loc = sel[s], g = cloud * NP + loc, oq = cloud * NS + s;
        g_fps[oq] = g;
        out_pos[oq * 3 + 0] = spos[loc * 3 + 0];
        out_pos[oq * 3 + 1] = spos[loc * 3 + 1];
        out_pos[oq * 3 + 2] = spos[loc * 3 + 2];
        out_batch[oq] = (float)batch[g];
    }
}

__global__ __launch_bounds__(256, 2) void fused_kernel(
    const float* __restrict__ A, const float* __restrict__ positions,
    const int* __restrict__ batch, const float* __restrict__ W,
    const float* __restrict__ bias,
    float* __restrict__ out_pos, float* __restrict__ out_batch) {
    extern __shared__ __align__(16) char smc[];
    if (blockIdx.x < 16) {
        fps_body(smc, positions, batch, out_pos, out_batch, blockIdx.x);
        return;
    }
    const int b = blockIdx.x - 16;
    const int bx = b & 3, by = b >> 2;
    float* As = (float*)smc;          // [2][8][128]
    float* Bs = As + 2 * 8 * 128;     // [2][8][128]
    const int tid = threadIdx.x;
    const int tx = tid & 15, ty = tid >> 4;
    const int arow = tid >> 1, half = tid & 1, acol = half * 4;
    const int brow = tid >> 5, bcol = (tid & 31) * 4;
    const float* aptr = A + (size_t)(by * 128 + arow) * NF + acol;
    const float* wbase = W + (size_t)brow * NO + bx * 128 + bcol;

    u64 acc2[8][4];
#pragma unroll
    for (int i = 0; i < 8; i++)
#pragma unroll
        for (int jp = 0; jp < 4; jp++) acc2[i][jp] = 0ull;
    float sq = 0.f;

    float4 av = *(const float4*)aptr;
    float4 bv = *(const float4*)wbase;
    for (int kb = 0; kb < 32; kb++) {
        float* Asb = As + (kb & 1) * 1024;
        float* Bsb = Bs + (kb & 1) * 1024;
        Asb[(acol + 0) * 128 + arow] = av.x;
        Asb[(acol + 1) * 128 + arow] = av.y;
        Asb[(acol + 2) * 128 + arow] = av.z;
        Asb[(acol + 3) * 128 + arow] = av.w;
        *(float4*)&Bsb[brow * 128 + bcol] = bv;
        if (bx == 0) {
            sq = fmaf(av.x, av.x, sq); sq = fmaf(av.y, av.y, sq);
            sq = fmaf(av.z, av.z, sq); sq = fmaf(av.w, av.w, sq);
        }
        __syncthreads();
        if (kb < 31) {
            av = *(const float4*)(aptr + (kb + 1) * 8);
            bv = *(const float4*)(wbase + (size_t)(kb + 1) * 8 * NO);
        }
#pragma unroll
        for (int k = 0; k < 8; k++) {
            float4 a0 = *(const float4*)&Asb[k * 128 + ty * 8];
            float4 a1 = *(const float4*)&Asb[k * 128 + ty * 8 + 4];
            const u64* bp = (const u64*)&Bsb[k * 128 + tx * 8];
            u64 b2[4] = {bp[0], bp[1], bp[2], bp[3]};
            u64 ad[8] = {dup2(a0.x), dup2(a0.y), dup2(a0.z), dup2(a0.w),
                         dup2(a1.x), dup2(a1.y), dup2(a1.z), dup2(a1.w)};
#pragma unroll
            for (int i = 0; i < 8; i++)
#pragma unroll
                for (int jp = 0; jp < 4; jp++)
                    FMA2(acc2[i][jp], ad[i], b2[jp]);
        }
    }

    if (bx == 0) {
        float o = __shfl_xor_sync(0xffffffffu, sq, 1);
        if (half == 0) g_hn[by * 128 + arow] = 0.5f * (sq + o);
    }

    const int ccol = bx * 128 + tx * 8;
    const int crow = by * 128 + ty * 8;
    float4 bb0 = *(const float4*)(bias + ccol);
    float4 bb1 = *(const float4*)(bias + ccol + 4);
#pragma unroll
    for (int i = 0; i < 8; i++) {
        float2 p0 = unpack2(acc2[i][0]), p1 = unpack2(acc2[i][1]);
        float2 p2 = unpack2(acc2[i][2]), p3 = unpack2(acc2[i][3]);
        float4 o0, o1;
        o0.x = p0.x + bb0.x; o0.y = p0.y + bb0.y;
        o0.z = p1.x + bb0.z; o0.w = p1.y + bb0.w;
        o1.x = p2.x + bb1.x; o1.y = p2.y + bb1.y;
        o1.z = p3.x + bb1.z; o1.w = p3.y + bb1.w;
        *(float4*)(g_h + (size_t)(crow + i) * NO + ccol) = o0;
        *(float4*)(g_h + (size_t)(crow + i) * NO + ccol + 4) = o1;
    }
}

// ===================== int8 quantization (1 warp per point) ==================
__global__ __launch_bounds__(256) void quant_kernel(const float* __restrict__ feat) {
    const int pt = blockIdx.x * 8 + (threadIdx.x >> 5);
    const int lane = threadIdx.x & 31;
    const float* f = feat + (size_t)pt * NF + lane * 8;
    float4 v0 = *(const float4*)f;
    float4 v1 = *(const float4*)(f + 4);
    float m = fmaxf(fmaxf(fmaxf(fabsf(v0.x), fabsf(v0.y)), fmaxf(fabsf(v0.z), fabsf(v0.w))),
                    fmaxf(fmaxf(fabsf(v1.x), fabsf(v1.y)), fmaxf(fabsf(v1.z), fabsf(v1.w))));
#pragma unroll
    for (int off = 16; off > 0; off >>= 1)
        m = fmaxf(m, __shfl_xor_sync(0xffffffffu, m, off));
    m = fmaxf(m, 1e-30f);
    float inv = 127.0f / m;
    int q[8];
    const float* vv0 = &v0.x;
    const float* vv1 = &v1.x;
#pragma unroll
    for (int j = 0; j < 4; j++) {
        q[j]     = max(-127, min(127, __float2int_rn(vv0[j] * inv)));
        q[j + 4] = max(-127, min(127, __float2int_rn(vv1[j] * inv)));
    }
    uint32_t p0 = (q[0] & 255) | ((q[1] & 255) << 8) | ((q[2] & 255) << 16) | ((uint32_t)(q[3] & 255) << 24);
    uint32_t p1 = (q[4] & 255) | ((q[5] & 255) << 8) | ((q[6] & 255) << 16) | ((uint32_t)(q[7] & 255) << 24);
    g_q8[(size_t)pt * 64 + lane * 2]     = p0;
    g_q8[(size_t)pt * 64 + lane * 2 + 1] = p1;
    if (lane == 0) g_qs[pt] = m * (1.0f / 127.0f);
}

// ===================== BN stats =====================
__global__ __launch_bounds__(512) void stats_partial_kernel() {
    int c = threadIdx.x, blk = blockIdx.x;
    float s = 0.f, s2 = 0.f;
    int r0 = blk * 512;
    for (int r = 0; r < 512; r++) {
        float v = g_h[(size_t)(r0 + r) * NO + c];
        s += v; s2 = fmaf(v, v, s2);
    }
    g_part[blk * NO + c] = s;
    g_part[128 * NO + blk * NO + c] = s2;
}
__global__ __launch_bounds__(512) void stats_final_kernel(const float* __restrict__ gamma,
                                                          const float* __restrict__ beta) {
    int c = threadIdx.x;
    float s = 0.f, s2 = 0.f;
    for (int b = 0; b < 128; b++) { s += g_part[b * NO + c]; s2 += g_part[128 * NO + b * NO + c]; }
    float inv = 1.0f / (float)NPTS;
    float mu = s * inv, var = s2 * inv - mu * mu;
    float a = gamma[c] * rsqrtf(var + 1e-5f);
    g_a[c] = a; g_c[c] = beta[c] - mu * a;
}

// ===================== KNN int8 v2: pipelined, occ-2, top-24 per segment =====
// Q tile resident (32KB), X streamed in 4 double-buffered chunks of 16 u32-k,
// scores staged + selected in two 64-column halves (order-independent select).
#define I_Q  0                              // 64 u32-k x 128 rows = 32768
#define I_X  (I_Q + 32768)                  // 2 x (16 u32-k x 128) = 16384
#define I_SC (I_X + 16384)                  // 128 x 65 int = 33280
#define I_SX (I_SC + 33280)                 // 128 floats
#define I_HN (I_SX + 512)                   // 128 floats
#define I_TV (I_HN + 512)                   // 128 x 24 float
#define I_TI (I_TV + 128*NKC*4)             // 128 x 24 int
#define KNN8_SMEM (I_TI + 128*NKC*4)        // 108032 -> 2 blocks/SM

__global__ __launch_bounds__(256, 2) void knn_i8_kernel() {
    extern __shared__ __align__(16) char smc[];
    uint32_t* Qs  = (uint32_t*)(smc + I_Q);
    uint32_t* Xs  = (uint32_t*)(smc + I_X);
    int*   Sc   = (int*)(smc + I_SC);
    float* sx_s = (float*)(smc + I_SX);
    float* hn_s = (float*)(smc + I_HN);
    float* topv = (float*)(smc + I_TV);
    int*   topi = (int*)(smc + I_TI);

    const int qt = blockIdx.x, sg = blockIdx.y, cloud = blockIdx.z;
    const int tid = threadIdx.x;
    const int tx = tid & 15, ty = tid >> 4;
    const int qbase = cloud * NS + qt * 128;

    // Q tile resident, k-major
    for (int i = tid; i < 2048; i += 256) {      // 128 rows x 16 uint4
        int row = i & 127, kg = i >> 7;
        int qr = g_fps[qbase + row];
        uint4 v = ((const uint4*)(g_q8 + (size_t)qr * 64))[kg];
        Qs[(kg * 4 + 0) * 128 + row] = v.x;
        Qs[(kg * 4 + 1) * 128 + row] = v.y;
        Qs[(kg * 4 + 2) * 128 + row] = v.z;
        Qs[(kg * 4 + 3) * 128 + row] = v.w;
    }
    if (tid < 128) {
#pragma unroll
        for (int r = 0; r < NKC; r++) {
            topv[tid * NKC + r] = NEG_INF;
            topi[tid * NKC + r] = 0x7fffffff;
        }
    }
    float sq_t = (tid < 128) ? g_qs[g_fps[qbase + tid]] : 0.f;
    const int xcloudbase = cloud * NP + sg * PSEG;

    // X loader mapping: slot s in {tid, tid+256}: row = s&127, kg = s>>7 (0..3)
    const int lr0 = tid & 127, lg0 = tid >> 7;       // slot tid
    const int lr1 = lr0, lg1 = lg0 + 2;              // slot tid+256
    __syncthreads();

    for (int t = 0; t < PSEG / 128; t++) {
        const int xbase = xcloudbase + t * 128;
        if (tid < 128) {
            sx_s[tid] = g_qs[xbase + tid];
            hn_s[tid] = g_hn[xbase + tid];
        }

        int acc[8][8];
#pragma unroll
        for (int i = 0; i < 8; i++)
#pragma unroll
            for (int j = 0; j < 8; j++) acc[i][j] = 0;

        // preload chunk 0
        uint4 xv0 = ((const uint4*)(g_q8 + (size_t)(xbase + lr0) * 64))[lg0];
        uint4 xv1 = ((const uint4*)(g_q8 + (size_t)(xbase + lr1) * 64))[lg1];

        for (int c = 0; c < 4; c++) {
            uint32_t* Xb = Xs + (c & 1) * 2048;
            Xb[(lg0 * 4 + 0) * 128 + lr0] = xv0.x;
            Xb[(lg0 * 4 + 1) * 128 + lr0] = xv0.y;
            Xb[(lg0 * 4 + 2) * 128 + lr0] = xv0.z;
            Xb[(lg0 * 4 + 3) * 128 + lr0] = xv0.w;
            Xb[(lg1 * 4 + 0) * 128 + lr1] = xv1.x;
            Xb[(lg1 * 4 + 1) * 128 + lr1] = xv1.y;
            Xb[(lg1 * 4 + 2) * 128 + lr1] = xv1.z;
            Xb[(lg1 * 4 + 3) * 128 + lr1] = xv1.w;
            __syncthreads();
            if (c < 3) {
                xv0 = ((const uint4*)(g_q8 + (size_t)(xbase + lr0) * 64))[(c + 1) * 4 + lg0];
                xv1 = ((const uint4*)(g_q8 + (size_t)(xbase + lr1) * 64))[(c + 1) * 4 + lg1];
            }
            const uint32_t* Qc = Qs + c * 16 * 128;
#pragma unroll 4
            for (int kk = 0; kk < 16; kk++) {
                uint4 a0 = *(const uint4*)&Qc[kk * 128 + ty * 8];
                uint4 a1 = *(const uint4*)&Qc[kk * 128 + ty * 8 + 4];
                uint4 b0 = *(const uint4*)&Xb[kk * 128 + tx * 8];
                uint4 b1 = *(const uint4*)&Xb[kk * 128 + tx * 8 + 4];
                int ar[8] = {(int)a0.x, (int)a0.y, (int)a0.z, (int)a0.w,
                             (int)a1.x, (int)a1.y, (int)a1.z, (int)a1.w};
                int br[8] = {(int)b0.x, (int)b0.y, (int)b0.z, (int)b0.w,
                             (int)b1.x, (int)b1.y, (int)b1.z, (int)b1.w};
#pragma unroll
                for (int i = 0; i < 8; i++)
#pragma unroll
                    for (int j = 0; j < 8; j++)
                        acc[i][j] = __dp4a(ar[i], br[j], acc[i][j]);
            }
        }
        __syncthreads();

        // two column-halves: stage + select (selection is order-independent)
#pragma unroll
        for (int half = 0; half < 2; half++) {
            if ((tx >> 3) == half) {
                int cx = (tx & 7) * 8;
#pragma unroll
                for (int i = 0; i < 8; i++)
#pragma unroll
                    for (int j = 0; j < 8; j++)
                        Sc[(ty * 8 + i) * 65 + cx + j] = acc[i][j];
            }
            __syncthreads();
            if (tid < 128) {
                const int* scr = Sc + tid * 65;
                float* tv = topv + tid * NKC;
                int*   ti = topi + tid * NKC;
                float th = tv[NKC - 1];
                int  thi = ti[NKC - 1];
                const int pb = half * 64;
                for (int p = 0; p < 64; p++) {
                    float s = sq_t * sx_s[pb + p] * (float)scr[p] - hn_s[pb + p];
                    int gi = xbase + pb + p;
                    if (s > th || (s == th && gi < thi)) {
                        int r = NKC - 1;
                        while (r > 0) {
                            float pv = tv[r - 1];
                            int   pi = ti[r - 1];
                            if (s > pv || (s == pv && gi < pi)) {
                                tv[r] = pv; ti[r] = pi; r--;
                            } else break;
                        }
                        tv[r] = s; ti[r] = gi;
                        th = tv[NKC - 1]; thi = ti[NKC - 1];
                    }
                }
            }
            __syncthreads();
        }
    }

    if (tid < 128) {
        int q = qbase + tid;
#pragma unroll
        for (int r = 0; r < NKC; r++)
            g_knni[((size_t)q * SEG + sg) * NKC + r] = topi[tid * NKC + r];
    }
}

// ===================== exact rescore of 96 candidates -> top-16 ==============
// Bit-identical round-1 arithmetic: ascending-k fmaf dot, s -= 0.5|x|^2,
// ordering by (score desc, index asc).
__global__ __launch_bounds__(128) void rescore_kernel(const float* __restrict__ feat) {
    __shared__ float q[NF];
    __shared__ float sv[SEG * NKC];
    __shared__ int   si[SEG * NKC];
    const int qi = blockIdx.x, tid = threadIdx.x;
    const int qg = g_fps[qi];
    q[tid]       = feat[(size_t)qg * NF + tid];
    q[tid + 128] = feat[(size_t)qg * NF + 128 + tid];
    __syncthreads();

    if (tid < SEG * NKC) {
        int gi = g_knni[(size_t)qi * SEG * NKC + tid];
        const float4* x = (const float4*)(feat + (size_t)gi * NF);
        float s = 0.f;
#pragma unroll 8
        for (int k4 = 0; k4 < NF / 4; k4++) {
            float4 xv = x[k4];
            s = fmaf(q[k4 * 4 + 0], xv.x, s);
            s = fmaf(q[k4 * 4 + 1], xv.y, s);
            s = fmaf(q[k4 * 4 + 2], xv.z, s);
            s = fmaf(q[k4 * 4 + 3], xv.w, s);
        }
        s -= g_hn[gi];
        sv[tid] = s;
        si[tid] = gi;
    }
    __syncthreads();

    if (tid < SEG * NKC) {
        float s = sv[tid];
        int gi = si[tid];
        int cnt = 0;
        for (int j = 0; j < SEG * NKC; j++) {
            float vj = sv[j];
            cnt += (vj > s || (vj == s && si[j] < gi)) ? 1 : 0;
        }
        if (cnt < NK) g_nn[(size_t)qi * NK + cnt] = gi;
    }
}

// ===================== gather + max-pool + BN + ReLU =========================
__global__ __launch_bounds__(128) void gather_kernel(float* __restrict__ out) {
    __shared__ int nn[NK];
    const int q = blockIdx.x, tid = threadIdx.x;
    if (tid < NK) nn[tid] = g_nn[(size_t)q * NK + tid];
    __syncthreads();
    float mx[4] = {NEG_INF, NEG_INF, NEG_INF, NEG_INF};
    float mn[4] = {POS_INF, POS_INF, POS_INF, POS_INF};
#pragma unroll
    for (int n = 0; n < NK; n++) {
        const float* hp = g_h + (size_t)nn[n] * NO;
#pragma unroll
        for (int j = 0; j < 4; j++) {
            float v = hp[tid + j * 128];
            mx[j] = fmaxf(mx[j], v); mn[j] = fminf(mn[j], v);
        }
    }
    float* op = out + (size_t)q * NO;
#pragma unroll
    for (int j = 0; j < 4; j++) {
        int c = tid + j * 128;
        float a = g_a[c], cc = g_c[c];
        float o = fmaxf(fmaf(a, mx[j], cc), fmaf(a, mn[j], cc));
        op[c] = fmaxf(o, 0.0f);
    }
}

// ===================== launch =====================
extern "C" void kernel_launch(void* const* d_in, const int* in_sizes, int n_in,
                              void* d_out, int out_size) {
    (void)in_sizes; (void)n_in; (void)out_size;
    const float* features  = (const float*)d_in[0];
    const float* positions = (const float*)d_in[1];
    const int*   batch     = (const int*)d_in[2];
    const float* W         = (const float*)d_in[3];
    const float* bias      = (const float*)d_in[4];
    const float* gamma     = (const float*)d_in[5];
    const float* beta      = (const float*)d_in[6];

    float* out       = (float*)d_out;
    float* out_feat  = out;
    float* out_pos   = out + (size_t)NQ * NO;
    float* out_batch = out_pos + (size_t)NQ * 3;

    cudaFuncSetAttribute(fused_kernel, cudaFuncAttributeMaxDynamicSharedMemorySize, FUSED_SMEM);
    cudaFuncSetAttribute(knn_i8_kernel, cudaFuncAttributeMaxDynamicSharedMemorySize, KNN8_SMEM);

    quant_kernel<<<NPTS / 8, 256>>>(features);
    fused_kernel<<<16 + 2048, 256, FUSED_SMEM>>>(features, positions, batch, W, bias,
                                                 out_pos, out_batch);
    stats_partial_kernel<<<128, 512>>>();
    knn_i8_kernel<<<dim3(8, SEG, NB), 256, KNN8_SMEM>>>();   // 4th launch -> ncu
    stats_final_kernel<<<1, 512>>>(gamma, beta);
    rescore_kernel<<<NQ, 128>>>(features);
    gather_kernel<<<NQ, 128>>>(out_feat);
}

// round 13
// speedup vs baseline: 1.3898x; 1.0336x over previous
#include <cuda_runtime.h>
#include <cstdint>
#include <cstddef>

#define NB 16
#define NP 4096
#define NS 1024
#define NK 16
#define NKC 24
#define NF 256
#define NO 512
#define NPTS (NB*NP)
#define NQ   (NB*NS)
#define SEG  4
#define PSEG (NP/SEG)

#define POS_INF __int_as_float(0x7f800000)
#define NEG_INF __int_as_float(0xff800000)

typedef unsigned long long u64;

__device__ float    g_h[(size_t)NPTS * NO];
__device__ float    g_hn[NPTS];
__device__ int      g_fps[NQ];
__device__ float    g_part[2 * 128 * NO];
__device__ float    g_a[NO];
__device__ float    g_c[NO];
__device__ uint32_t g_q8[(size_t)NPTS * 64];
__device__ float    g_qs[NPTS];
__device__ int      g_knni[(size_t)NQ * SEG * NKC];
__device__ int      g_nn[(size_t)NQ * NK];

// ---------------- f32x2 helpers (each half rounds exactly like scalar FFMA) --
__device__ __forceinline__ u64 dup2(float x) {
    u64 r;
    uint32_t b = __float_as_uint(x);
    asm("mov.b64 %0, {%1, %1};" : "=l"(r) : "r"(b));
    return r;
}
__device__ __forceinline__ u64 pack2(float x, float y) {
    u64 r;
    asm("mov.b64 %0, {%1, %2};" : "=l"(r) : "f"(x), "f"(y));
    return r;
}
#define FMA2(acc, a, b) \
    asm("fma.rn.f32x2 %0, %1, %2, %0;" : "+l"(acc) : "l"(a), "l"(b))
__device__ __forceinline__ float2 unpack2(u64 v) {
    float2 r;
    asm("mov.b64 {%0, %1}, %2;" : "=f"(r.x), "=f"(r.y) : "l"(v));
    return r;
}
// interleaved pair layout: pair cp at byte ((cp&3)*16 + (cp>>2))*8 in a 512B row
__device__ __forceinline__ int cp_off(int cp) { return ((cp & 3) * 16 + (cp >> 2)) * 8; }
// single u32 column c within that layout
__device__ __forceinline__ int xoff(int c) {
    return (((c >> 1) & 3) * 16 + (c >> 3)) * 8 + (c & 1) * 4;
}

// ===================== FPS body (bit-exact, proven R7) ========================
#define FPS_SMEM_BYTES ((NP * 3 + NS + 8 + 8 + 1) * 4)
#define FUSED_SMEM FPS_SMEM_BYTES

__device__ void fps_body(char* smc, const float* __restrict__ positions,
                         const int* __restrict__ batch,
                         float* __restrict__ out_pos, float* __restrict__ out_batch,
                         int cloud) {
    float* spos  = (float*)smc;
    int*   sel   = (int*)(spos + NP * 3);
    float* rv    = (float*)(sel + NS);
    int*   ri    = (int*)(rv + 8);
    int*   slast = ri + 8;
    const int tid = threadIdx.x;
    const float* pos = positions + (size_t)cloud * NP * 3;
    for (int i = tid; i < NP * 3; i += 256) spos[i] = pos[i];
    __syncthreads();

    float px[16], py[16], pz[16], md[16];
#pragma unroll
    for (int j = 0; j < 16; j++) {
        int pt = tid + j * 256;
        px[j] = spos[pt * 3]; py[j] = spos[pt * 3 + 1]; pz[j] = spos[pt * 3 + 2];
        md[j] = POS_INF;
    }
    if (tid == 0) sel[0] = 0;
    int last = 0;
    const int lane = tid & 31, warp = tid >> 5;
    for (int it = 1; it < NS; it++) {
        float lx = spos[last * 3], ly = spos[last * 3 + 1], lz = spos[last * 3 + 2];
        float bv = NEG_INF; int bi = 0x7fffffff;
#pragma unroll
        for (int j = 0; j < 16; j++) {
            float dx = px[j] - lx, dy = py[j] - ly, dz = pz[j] - lz;
            float d = __fadd_rn(__fadd_rn(__fmul_rn(dx, dx), __fmul_rn(dy, dy)),
                                __fmul_rn(dz, dz));
            float m = fminf(md[j], d);
            md[j] = m;
            if (m > bv) { bv = m; bi = tid + j * 256; }
        }
#pragma unroll
        for (int off = 16; off > 0; off >>= 1) {
            float ov = __shfl_down_sync(0xffffffffu, bv, off);
            int   oi = __shfl_down_sync(0xffffffffu, bi, off);
            if (ov > bv || (ov == bv && oi < bi)) { bv = ov; bi = oi; }
        }
        if (lane == 0) { rv[warp] = bv; ri[warp] = bi; }
        __syncthreads();
        if (warp == 0) {
            float v = (lane < 8) ? rv[lane] : NEG_INF;
            int b = (lane < 8) ? ri[lane] : 0x7fffffff;
#pragma unroll
            for (int off = 4; off > 0; off >>= 1) {
                float ov = __shfl_down_sync(0xffffffffu, v, off);
                int   oi = __shfl_down_sync(0xffffffffu, b, off);
                if (ov > v || (ov == v && oi < b)) { v = ov; b = oi; }
            }
            if (lane == 0) { sel[it] = b; slast[0] = b; }
        }
        __syncthreads();
        last = slast[0];
    }
    for (int s = tid; s < NS; s += 256) {
        int loc = sel[s], g = cloud * NP + loc, oq = cloud * NS + s;
        g_fps[oq] = g;
        out_pos[oq * 3 + 0] = spos[loc * 3 + 0];
        out_pos[oq * 3 + 1] = spos[loc * 3 + 1];
        out_pos[oq * 3 + 2] = spos[loc * 3 + 2];
        out_batch[oq] = (float)batch[g];
    }
}

// ===================== fused FPS + MLP GEMM (conflict-free B) =================
__global__ __launch_bounds__(256, 2) void fused_kernel(
    const float* __restrict__ A, const float* __restrict__ positions,
    const int* __restrict__ batch, const float* __restrict__ W,
    const float* __restrict__ bias,
    float* __restrict__ out_pos, float* __restrict__ out_batch) {
    extern __shared__ __align__(16) char smc[];
    if (blockIdx.x < 16) {
        fps_body(smc, positions, batch, out_pos, out_batch, blockIdx.x);
        return;
    }
    const int b = blockIdx.x - 16;
    const int bx = b & 3, by = b >> 2;
    float* As = (float*)smc;              // [2][8][128] col-major
    char*  Bm = smc + 2 * 8 * 128 * 4;    // [2][8 rows x 512B] interleaved pairs
    const int tid = threadIdx.x;
    const int tx = tid & 15, ty = tid >> 4;
    const int arow = tid >> 1, acol = (tid & 1) * 4;
    const int brow = tid >> 5, bcol = (tid & 31) * 4;
    const float* aptr = A + (size_t)(by * 128 + arow) * NF + acol;
    const float* wbase = W + (size_t)brow * NO + bx * 128 + bcol;
    const int wo0 = cp_off(bcol >> 1), wo1 = cp_off((bcol >> 1) + 1);

    u64 acc2[8][4];
#pragma unroll
    for (int i = 0; i < 8; i++)
#pragma unroll
        for (int jp = 0; jp < 4; jp++) acc2[i][jp] = 0ull;

    float4 av = *(const float4*)aptr;
    float4 wv = *(const float4*)wbase;
    for (int kb = 0; kb < 32; kb++) {
        float* Asb = As + (kb & 1) * 1024;
        char*  Bsb = Bm + (kb & 1) * 4096;
        Asb[(acol + 0) * 128 + arow] = av.x;
        Asb[(acol + 1) * 128 + arow] = av.y;
        Asb[(acol + 2) * 128 + arow] = av.z;
        Asb[(acol + 3) * 128 + arow] = av.w;
        {
            char* wrow = Bsb + brow * 512;
            *(u64*)(wrow + wo0) = pack2(wv.x, wv.y);
            *(u64*)(wrow + wo1) = pack2(wv.z, wv.w);
        }
        __syncthreads();
        if (kb < 31) {
            av = *(const float4*)(aptr + (kb + 1) * 8);
            wv = *(const float4*)(wbase + (size_t)(kb + 1) * 8 * NO);
        }
#pragma unroll
        for (int k = 0; k < 8; k++) {
            float4 a0 = *(const float4*)&Asb[k * 128 + ty * 8];
            float4 a1 = *(const float4*)&Asb[k * 128 + ty * 8 + 4];
            const char* brow_p = Bsb + k * 512;
            u64 b2[4];
#pragma unroll
            for (int jp = 0; jp < 4; jp++)
                b2[jp] = *(const u64*)(brow_p + (jp * 16 + tx) * 8);
            u64 ad[8] = {dup2(a0.x), dup2(a0.y), dup2(a0.z), dup2(a0.w),
                         dup2(a1.x), dup2(a1.y), dup2(a1.z), dup2(a1.w)};
#pragma unroll
            for (int i = 0; i < 8; i++)
#pragma unroll
                for (int jp = 0; jp < 4; jp++)
                    FMA2(acc2[i][jp], ad[i], b2[jp]);
        }
        __syncthreads();
    }

    const int ccol = bx * 128 + tx * 8;
    const int crow = by * 128 + ty * 8;
    float4 bb0 = *(const float4*)(bias + ccol);
    float4 bb1 = *(const float4*)(bias + ccol + 4);
#pragma unroll
    for (int i = 0; i < 8; i++) {
        float2 p0 = unpack2(acc2[i][0]), p1 = unpack2(acc2[i][1]);
        float2 p2 = unpack2(acc2[i][2]), p3 = unpack2(acc2[i][3]);
        float4 o0, o1;
        o0.x = p0.x + bb0.x; o0.y = p0.y + bb0.y;
        o0.z = p1.x + bb0.z; o0.w = p1.y + bb0.w;
        o1.x = p2.x + bb1.x; o1.y = p2.y + bb1.y;
        o1.z = p3.x + bb1.z; o1.w = p3.y + bb1.w;
        *(float4*)(g_h + (size_t)(crow + i) * NO + ccol) = o0;
        *(float4*)(g_h + (size_t)(crow + i) * NO + ccol + 4) = o1;
    }
}

// ===================== xnorm (R1-proven, hn = 0.5|x|^2) ======================
__global__ __launch_bounds__(128) void xnorm_kernel(const float* __restrict__ feat) {
    int row = blockIdx.x * 4 + (threadIdx.x >> 5);
    int lane = threadIdx.x & 31;
    const float* f = feat + (size_t)row * NF;
    float s = 0.f;
#pragma unroll
    for (int i = 0; i < NF / 32; i++) {
        float v = f[lane + 32 * i];
        s = fmaf(v, v, s);
    }
#pragma unroll
    for (int off = 16; off > 0; off >>= 1) s += __shfl_down_sync(0xffffffffu, s, off);
    if (lane == 0) g_hn[row] = 0.5f * s;
}

// ===================== int8 quantization (1 warp per point, half grid) =======
__global__ __launch_bounds__(256) void quant_kernel(const float* __restrict__ feat, int base) {
    const int pt = base + blockIdx.x * 8 + (threadIdx.x >> 5);
    const int lane = threadIdx.x & 31;
    const float* f = feat + (size_t)pt * NF + lane * 8;
    float4 v0 = *(const float4*)f;
    float4 v1 = *(const float4*)(f + 4);
    float m = fmaxf(fmaxf(fmaxf(fabsf(v0.x), fabsf(v0.y)), fmaxf(fabsf(v0.z), fabsf(v0.w))),
                    fmaxf(fmaxf(fabsf(v1.x), fabsf(v1.y)), fmaxf(fabsf(v1.z), fabsf(v1.w))));
#pragma unroll
    for (int off = 16; off > 0; off >>= 1)
        m = fmaxf(m, __shfl_xor_sync(0xffffffffu, m, off));
    m = fmaxf(m, 1e-30f);
    float inv = 127.0f / m;
    int q[8];
    const float* vv0 = &v0.x;
    const float* vv1 = &v1.x;
#pragma unroll
    for (int j = 0; j < 4; j++) {
        q[j]     = max(-127, min(127, __float2int_rn(vv0[j] * inv)));
        q[j + 4] = max(-127, min(127, __float2int_rn(vv1[j] * inv)));
    }
    uint32_t p0 = (q[0] & 255) | ((q[1] & 255) << 8) | ((q[2] & 255) << 16) | ((uint32_t)(q[3] & 255) << 24);
    uint32_t p1 = (q[4] & 255) | ((q[5] & 255) << 8) | ((q[6] & 255) << 16) | ((uint32_t)(q[7] & 255) << 24);
    g_q8[(size_t)pt * 64 + lane * 2]     = p0;
    g_q8[(size_t)pt * 64 + lane * 2 + 1] = p1;
    if (lane == 0) g_qs[pt] = m * (1.0f / 127.0f);
}

// ===================== BN stats =====================
__global__ __launch_bounds__(512) void stats_partial_kernel() {
    int c = threadIdx.x, blk = blockIdx.x;
    float s = 0.f, s2 = 0.f;
    int r0 = blk * 512;
    for (int r = 0; r < 512; r++) {
        float v = g_h[(size_t)(r0 + r) * NO + c];
        s += v; s2 = fmaf(v, v, s2);
    }
    g_part[blk * NO + c] = s;
    g_part[128 * NO + blk * NO + c] = s2;
}
__global__ __launch_bounds__(512) void stats_final_kernel(const float* __restrict__ gamma,
                                                          const float* __restrict__ beta) {
    int c = threadIdx.x;
    float s = 0.f, s2 = 0.f;
    for (int b = 0; b < 128; b++) { s += g_part[b * NO + c]; s2 += g_part[128 * NO + b * NO + c]; }
    float inv = 1.0f / (float)NPTS;
    float mu = s * inv, var = s2 * inv - mu * mu;
    float a = gamma[c] * rsqrtf(var + 1e-5f);
    g_a[c] = a; g_c[c] = beta[c] - mu * a;
}

// ===================== KNN int8 v3: conflict-free X, occ-2 ===================
#define I_Q  0                              // 64 u32-k x 128 rows = 32768
#define I_X  (I_Q + 32768)                  // 2 x (16 k x 512B) = 16384
#define I_SC (I_X + 16384)                  // 128 x 65 int = 33280
#define I_SX (I_SC + 33280)
#define I_HN (I_SX + 512)
#define I_TV (I_HN + 512)
#define I_TI (I_TV + 128*NKC*4)
#define KNN8_SMEM (I_TI + 128*NKC*4)        // 108032 -> 2 blocks/SM

__global__ __launch_bounds__(256, 2) void knn_i8_kernel() {
    extern __shared__ __align__(16) char smc[];
    uint32_t* Qs  = (uint32_t*)(smc + I_Q);
    char*  Xm   = smc + I_X;
    int*   Sc   = (int*)(smc + I_SC);
    float* sx_s = (float*)(smc + I_SX);
    float* hn_s = (float*)(smc + I_HN);
    float* topv = (float*)(smc + I_TV);
    int*   topi = (int*)(smc + I_TI);

    const int qt = blockIdx.x, sg = blockIdx.y, cloud = blockIdx.z;
    const int tid = threadIdx.x;
    const int tx = tid & 15, ty = tid >> 4;
    const int qbase = cloud * NS + qt * 128;

    // Q tile resident, k-major
    for (int i = tid; i < 2048; i += 256) {
        int row = i & 127, kg = i >> 7;
        int qr = g_fps[qbase + row];
        uint4 v = ((const uint4*)(g_q8 + (size_t)qr * 64))[kg];
        Qs[(kg * 4 + 0) * 128 + row] = v.x;
        Qs[(kg * 4 + 1) * 128 + row] = v.y;
        Qs[(kg * 4 + 2) * 128 + row] = v.z;
        Qs[(kg * 4 + 3) * 128 + row] = v.w;
    }
    if (tid < 128) {
#pragma unroll
        for (int r = 0; r < NKC; r++) {
            topv[tid * NKC + r] = NEG_INF;
            topi[tid * NKC + r] = 0x7fffffff;
        }
    }
    float sq_t = (tid < 128) ? g_qs[g_fps[qbase + tid]] : 0.f;
    const int xcloudbase = cloud * NP + sg * PSEG;

    const int lr0 = tid & 127, lg0 = tid >> 7;       // slot tid:     kg = lg0 (0..1)
    const int lg1 = lg0 + 2;                         // slot tid+256: kg = lg1 (2..3)
    const int xo = xoff(lr0);                        // interleaved column offset
    __syncthreads();

    for (int t = 0; t < PSEG / 128; t++) {
        const int xbase = xcloudbase + t * 128;
        if (tid < 128) {
            sx_s[tid] = g_qs[xbase + tid];
            hn_s[tid] = g_hn[xbase + tid];
        }

        int acc[8][8];
#pragma unroll
        for (int i = 0; i < 8; i++)
#pragma unroll
            for (int j = 0; j < 8; j++) acc[i][j] = 0;

        uint4 xv0 = ((const uint4*)(g_q8 + (size_t)(xbase + lr0) * 64))[lg0];
        uint4 xv1 = ((const uint4*)(g_q8 + (size_t)(xbase + lr0) * 64))[lg1];

        for (int c = 0; c < 4; c++) {
            char* Xb = Xm + (c & 1) * 8192;
            {
                char* r0 = Xb + (lg0 * 4) * 512 + xo;      // local k-rows 0..7
                *(uint32_t*)(r0)         = xv0.x;
                *(uint32_t*)(r0 + 512)   = xv0.y;
                *(uint32_t*)(r0 + 1024)  = xv0.z;
                *(uint32_t*)(r0 + 1536)  = xv0.w;
                char* r1 = Xb + (lg1 * 4) * 512 + xo;      // local k-rows 8..15 (BUGFIX)
                *(uint32_t*)(r1)         = xv1.x;
                *(uint32_t*)(r1 + 512)   = xv1.y;
                *(uint32_t*)(r1 + 1024)  = xv1.z;
                *(uint32_t*)(r1 + 1536)  = xv1.w;
            }
            __syncthreads();
            if (c < 3) {
                xv0 = ((const uint4*)(g_q8 + (size_t)(xbase + lr0) * 64))[(c + 1) * 4 + lg0];
                xv1 = ((const uint4*)(g_q8 + (size_t)(xbase + lr0) * 64))[(c + 1) * 4 + lg1];
            }
            const uint32_t* Qc = Qs + c * 16 * 128;
#pragma unroll 4
            for (int kk = 0; kk < 16; kk++) {
                uint4 a0 = *(const uint4*)&Qc[kk * 128 + ty * 8];
                uint4 a1 = *(const uint4*)&Qc[kk * 128 + ty * 8 + 4];
                const char* xrow = Xb + kk * 512;
                uint2 bq0 = *(const uint2*)(xrow + (0 * 16 + tx) * 8);
                uint2 bq1 = *(const uint2*)(xrow + (1 * 16 + tx) * 8);
                uint2 bq2 = *(const uint2*)(xrow + (2 * 16 + tx) * 8);
                uint2 bq3 = *(const uint2*)(xrow + (3 * 16 + tx) * 8);
                int ar[8] = {(int)a0.x, (int)a0.y, (int)a0.z, (int)a0.w,
                             (int)a1.x, (int)a1.y, (int)a1.z, (int)a1.w};
                int br[8] = {(int)bq0.x, (int)bq0.y, (int)bq1.x, (int)bq1.y,
                             (int)bq2.x, (int)bq2.y, (int)bq3.x, (int)bq3.y};
#pragma unroll
                for (int i = 0; i < 8; i++)
#pragma unroll
                    for (int j = 0; j < 8; j++)
                        acc[i][j] = __dp4a(ar[i], br[j], acc[i][j]);
            }
        }
        __syncthreads();

#pragma unroll
        for (int half = 0; half < 2; half++) {
            if ((tx >> 3) == half) {
                int cx = (tx & 7) * 8;
#pragma unroll
                for (int i = 0; i < 8; i++)
#pragma unroll
                    for (int j = 0; j < 8; j++)
                        Sc[(ty * 8 + i) * 65 + cx + j] = acc[i][j];
            }
            __syncthreads();
            if (tid < 128) {
                const int* scr = Sc + tid * 65;
                float* tv = topv + tid * NKC;
                int*   ti = topi + tid * NKC;
                float th = tv[NKC - 1];
                int  thi = ti[NKC - 1];
                const int pb = half * 64;
                for (int p = 0; p < 64; p++) {
                    float s = sq_t * sx_s[pb + p] * (float)scr[p] - hn_s[pb + p];
                    int gi = xbase + pb + p;
                    if (s > th || (s == th && gi < thi)) {
                        int r = NKC - 1;
                        while (r > 0) {
                            float pv = tv[r - 1];
                            int   pi = ti[r - 1];
                            if (s > pv || (s == pv && gi < pi)) {
                                tv[r] = pv; ti[r] = pi; r--;
                            } else break;
                        }
                        tv[r] = s; ti[r] = gi;
                        th = tv[NKC - 1]; thi = ti[NKC - 1];
                    }
                }
            }
            __syncthreads();
        }
    }

    if (tid < 128) {
        int q = qbase + tid;
#pragma unroll
        for (int r = 0; r < NKC; r++)
            g_knni[((size_t)q * SEG + sg) * NKC + r] = topi[tid * NKC + r];
    }
}

// ===================== exact rescore of 96 candidates -> top-16 ==============
__global__ __launch_bounds__(128) void rescore_kernel(const float* __restrict__ feat) {
    __shared__ float q[NF];
    __shared__ float sv[SEG * NKC];
    __shared__ int   si[SEG * NKC];
    const int qi = blockIdx.x, tid = threadIdx.x;
    const int qg = g_fps[qi];
    q[tid]       = feat[(size_t)qg * NF + tid];
    q[tid + 128] = feat[(size_t)qg * NF + 128 + tid];
    __syncthreads();

    if (tid < SEG * NKC) {
        int gi = g_knni[(size_t)qi * SEG * NKC + tid];
        const float4* x = (const float4*)(feat + (size_t)gi * NF);
        float s = 0.f;
#pragma unroll 8
        for (int k4 = 0; k4 < NF / 4; k4++) {
            float4 xv = x[k4];
            s = fmaf(q[k4 * 4 + 0], xv.x, s);
            s = fmaf(q[k4 * 4 + 1], xv.y, s);
            s = fmaf(q[k4 * 4 + 2], xv.z, s);
            s = fmaf(q[k4 * 4 + 3], xv.w, s);
        }
        s -= g_hn[gi];
        sv[tid] = s;
        si[tid] = gi;
    }
    __syncthreads();

    if (tid < SEG * NKC) {
        float s = sv[tid];
        int gi = si[tid];
        int cnt = 0;
        for (int j = 0; j < SEG * NKC; j++) {
            float vj = sv[j];
            cnt += (vj > s || (vj == s && si[j] < gi)) ? 1 : 0;
        }
        if (cnt < NK) g_nn[(size_t)qi * NK + cnt] = gi;
    }
}

// ===================== gather + max-pool + BN + ReLU =========================
__global__ __launch_bounds__(128) void gather_kernel(float* __restrict__ out) {
    __shared__ int nn[NK];
    const int q = blockIdx.x, tid = threadIdx.x;
    if (tid < NK) nn[tid] = g_nn[(size_t)q * NK + tid];
    __syncthreads();
    float mx[4] = {NEG_INF, NEG_INF, NEG_INF, NEG_INF};
    float mn[4] = {POS_INF, POS_INF, POS_INF, POS_INF};
#pragma unroll
    for (int n = 0; n < NK; n++) {
        const float* hp = g_h + (size_t)nn[n] * NO;
#pragma unroll
        for (int j = 0; j < 4; j++) {
            float v = hp[tid + j * 128];
            mx[j] = fmaxf(mx[j], v); mn[j] = fminf(mn[j], v);
        }
    }
    float* op = out + (size_t)q * NO;
#pragma unroll
    for (int j = 0; j < 4; j++) {
        int c = tid + j * 128;
        float a = g_a[c], cc = g_c[c];
        float o = fmaxf(fmaf(a, mx[j], cc), fmaf(a, mn[j], cc));
        op[c] = fmaxf(o, 0.0f);
    }
}

// ===================== launch =====================
extern "C" void kernel_launch(void* const* d_in, const int* in_sizes, int n_in,
                              void* d_out, int out_size) {
    (void)in_sizes; (void)n_in; (void)out_size;
    const float* features  = (const float*)d_in[0];
    const float* positions = (const float*)d_in[1];
    const int*   batch     = (const int*)d_in[2];
    const float* W         = (const float*)d_in[3];
    const float* bias      = (const float*)d_in[4];
    const float* gamma     = (const float*)d_in[5];
    const float* beta      = (const float*)d_in[6];

    float* out       = (float*)d_out;
    float* out_feat  = out;
    float* out_pos   = out + (size_t)NQ * NO;
    float* out_batch = out_pos + (size_t)NQ * 3;

    cudaFuncSetAttribute(fused_kernel, cudaFuncAttributeMaxDynamicSharedMemorySize, FUSED_SMEM);
    cudaFuncSetAttribute(knn_i8_kernel, cudaFuncAttributeMaxDynamicSharedMemorySize, KNN8_SMEM);

    quant_kernel<<<NPTS / 16, 256>>>(features, 0);
    quant_kernel<<<NPTS / 16, 256>>>(features, NPTS / 2);
    xnorm_kernel<<<NPTS / 4, 128>>>(features);
    fused_kernel<<<16 + 2048, 256, FUSED_SMEM>>>(features, positions, batch, W, bias,
                                                 out_pos, out_batch);   // 4th -> ncu
    stats_partial_kernel<<<128, 512>>>();
    knn_i8_kernel<<<dim3(8, SEG, NB), 256, KNN8_SMEM>>>();
    stats_final_kernel<<<1, 512>>>(gamma, beta);
    rescore_kernel<<<NQ, 128>>>(features);
    gather_kernel<<<NQ, 128>>>(out_feat);
}

// round 14
// speedup vs baseline: 1.7625x; 1.2681x over previous
#include <cuda_runtime.h>
#include <cstdint>
#include <cstddef>

#define NB 16
#define NP 4096
#define NS 1024
#define NK 16
#define NKC 24
#define NF 256
#define NO 512
#define NPTS (NB*NP)
#define NQ   (NB*NS)
#define SEG  2
#define PSEG (NP/SEG)   // 2048
#define NCAND (SEG*NKC) // 48

#define POS_INF __int_as_float(0x7f800000)
#define NEG_INF __int_as_float(0xff800000)

typedef unsigned long long u64;

__device__ float    g_h[(size_t)NPTS * NO];
__device__ float    g_hn[NPTS];
__device__ int      g_fps[NQ];
__device__ float    g_part[2 * 128 * NO];
__device__ float    g_a[NO];
__device__ float    g_c[NO];
__device__ uint32_t g_q8[(size_t)NPTS * 64];
__device__ float    g_qs[NPTS];
__device__ int      g_knni[(size_t)NQ * NCAND];

// ---------------- f32x2 helpers (each half rounds exactly like scalar FFMA) --
__device__ __forceinline__ u64 dup2(float x) {
    u64 r;
    uint32_t b = __float_as_uint(x);
    asm("mov.b64 %0, {%1, %1};" : "=l"(r) : "r"(b));
    return r;
}
__device__ __forceinline__ u64 pack2(float x, float y) {
    u64 r;
    asm("mov.b64 %0, {%1, %2};" : "=l"(r) : "f"(x), "f"(y));
    return r;
}
#define FMA2(acc, a, b) \
    asm("fma.rn.f32x2 %0, %1, %2, %0;" : "+l"(acc) : "l"(a), "l"(b))
__device__ __forceinline__ float2 unpack2(u64 v) {
    float2 r;
    asm("mov.b64 {%0, %1}, %2;" : "=f"(r.x), "=f"(r.y) : "l"(v));
    return r;
}
// interleaved pair layout: pair cp at byte ((cp&3)*16 + (cp>>2))*8 in a 512B row
__device__ __forceinline__ int cp_off(int cp) { return ((cp & 3) * 16 + (cp >> 2)) * 8; }
__device__ __forceinline__ int xoff(int c) {
    return (((c >> 1) & 3) * 16 + (c >> 3)) * 8 + (c & 1) * 4;
}

// ===================== FPS body (bit-exact) ==================================
#define FPS_SMEM_BYTES ((NP * 3 + NS + 8 + 8 + 1) * 4)
#define FUSED_SMEM FPS_SMEM_BYTES

__device__ void fps_body(char* smc, const float* __restrict__ positions,
                         const int* __restrict__ batch,
                         float* __restrict__ out_pos, float* __restrict__ out_batch,
                         int cloud) {
    float* spos  = (float*)smc;
    int*   sel   = (int*)(spos + NP * 3);
    float* rv    = (float*)(sel + NS);
    int*   ri    = (int*)(rv + 8);
    int*   slast = ri + 8;
    const int tid = threadIdx.x;
    const float* pos = positions + (size_t)cloud * NP * 3;
    for (int i = tid; i < NP * 3; i += 256) spos[i] = pos[i];
    __syncthreads();

    float px[16], py[16], pz[16], md[16];
#pragma unroll
    for (int j = 0; j < 16; j++) {
        int pt = tid + j * 256;
        px[j] = spos[pt * 3]; py[j] = spos[pt * 3 + 1]; pz[j] = spos[pt * 3 + 2];
        md[j] = POS_INF;
    }
    if (tid == 0) sel[0] = 0;
    int last = 0;
    const int lane = tid & 31, warp = tid >> 5;
    for (int it = 1; it < NS; it++) {
        float lx = spos[last * 3], ly = spos[last * 3 + 1], lz = spos[last * 3 + 2];
        float bv = NEG_INF; int bi = 0x7fffffff;
#pragma unroll
        for (int j = 0; j < 16; j++) {
            float dx = px[j] - lx, dy = py[j] - ly, dz = pz[j] - lz;
            float d = __fadd_rn(__fadd_rn(__fmul_rn(dx, dx), __fmul_rn(dy, dy)),
                                __fmul_rn(dz, dz));
            float m = fminf(md[j], d);
            md[j] = m;
            if (m > bv) { bv = m; bi = tid + j * 256; }
        }
#pragma unroll
        for (int off = 16; off > 0; off >>= 1) {
            float ov = __shfl_down_sync(0xffffffffu, bv, off);
            int   oi = __shfl_down_sync(0xffffffffu, bi, off);
            if (ov > bv || (ov == bv && oi < bi)) { bv = ov; bi = oi; }
        }
        if (lane == 0) { rv[warp] = bv; ri[warp] = bi; }
        __syncthreads();
        if (warp == 0) {
            float v = (lane < 8) ? rv[lane] : NEG_INF;
            int b = (lane < 8) ? ri[lane] : 0x7fffffff;
#pragma unroll
            for (int off = 4; off > 0; off >>= 1) {
                float ov = __shfl_down_sync(0xffffffffu, v, off);
                int   oi = __shfl_down_sync(0xffffffffu, b, off);
                if (ov > v || (ov == v && oi < b)) { v = ov; b = oi; }
            }
            if (lane == 0) { sel[it] = b; slast[0] = b; }
        }
        __syncthreads();
        last = slast[0];
    }
    for (int s = tid; s < NS; s += 256) {
        int loc = sel[s], g = cloud * NP + loc, oq = cloud * NS + s;
        g_fps[oq] = g;
        out_pos[oq * 3 + 0] = spos[loc * 3 + 0];
        out_pos[oq * 3 + 1] = spos[loc * 3 + 1];
        out_pos[oq * 3 + 2] = spos[loc * 3 + 2];
        out_batch[oq] = (float)batch[g];
    }
}

// ===================== fused FPS + MLP GEMM (conflict-free B) =================
__global__ __launch_bounds__(256, 2) void fused_kernel(
    const float* __restrict__ A, const float* __restrict__ positions,
    const int* __restrict__ batch, const float* __restrict__ W,
    const float* __restrict__ bias,
    float* __restrict__ out_pos, float* __restrict__ out_batch) {
    extern __shared__ __align__(16) char smc[];
    if (blockIdx.x < 16) {
        fps_body(smc, positions, batch, out_pos, out_batch, blockIdx.x);
        return;
    }
    const int b = blockIdx.x - 16;
    const int bx = b & 3, by = b >> 2;
    float* As = (float*)smc;              // [2][8][128] col-major
    char*  Bm = smc + 2 * 8 * 128 * 4;    // [2][8 rows x 512B] interleaved pairs
    const int tid = threadIdx.x;
    const int tx = tid & 15, ty = tid >> 4;
    const int arow = tid >> 1, acol = (tid & 1) * 4;
    const int brow = tid >> 5, bcol = (tid & 31) * 4;
    const float* aptr = A + (size_t)(by * 128 + arow) * NF + acol;
    const float* wbase = W + (size_t)brow * NO + bx * 128 + bcol;
    const int wo0 = cp_off(bcol >> 1), wo1 = cp_off((bcol >> 1) + 1);

    u64 acc2[8][4];
#pragma unroll
    for (int i = 0; i < 8; i++)
#pragma unroll
        for (int jp = 0; jp < 4; jp++) acc2[i][jp] = 0ull;

    float4 av = *(const float4*)aptr;
    float4 wv = *(const float4*)wbase;
    for (int kb = 0; kb < 32; kb++) {
        float* Asb = As + (kb & 1) * 1024;
        char*  Bsb = Bm + (kb & 1) * 4096;
        Asb[(acol + 0) * 128 + arow] = av.x;
        Asb[(acol + 1) * 128 + arow] = av.y;
        Asb[(acol + 2) * 128 + arow] = av.z;
        Asb[(acol + 3) * 128 + arow] = av.w;
        {
            char* wrow = Bsb + brow * 512;
            *(u64*)(wrow + wo0) = pack2(wv.x, wv.y);
            *(u64*)(wrow + wo1) = pack2(wv.z, wv.w);
        }
        __syncthreads();
        if (kb < 31) {
            av = *(const float4*)(aptr + (kb + 1) * 8);
            wv = *(const float4*)(wbase + (size_t)(kb + 1) * 8 * NO);
        }
#pragma unroll
        for (int k = 0; k < 8; k++) {
            float4 a0 = *(const float4*)&Asb[k * 128 + ty * 8];
            float4 a1 = *(const float4*)&Asb[k * 128 + ty * 8 + 4];
            const char* brow_p = Bsb + k * 512;
            u64 b2[4];
#pragma unroll
            for (int jp = 0; jp < 4; jp++)
                b2[jp] = *(const u64*)(brow_p + (jp * 16 + tx) * 8);
            u64 ad[8] = {dup2(a0.x), dup2(a0.y), dup2(a0.z), dup2(a0.w),
                         dup2(a1.x), dup2(a1.y), dup2(a1.z), dup2(a1.w)};
#pragma unroll
            for (int i = 0; i < 8; i++)
#pragma unroll
                for (int jp = 0; jp < 4; jp++)
                    FMA2(acc2[i][jp], ad[i], b2[jp]);
        }
        __syncthreads();
    }

    const int ccol = bx * 128 + tx * 8;
    const int crow = by * 128 + ty * 8;
    float4 bb0 = *(const float4*)(bias + ccol);
    float4 bb1 = *(const float4*)(bias + ccol + 4);
#pragma unroll
    for (int i = 0; i < 8; i++) {
        float2 p0 = unpack2(acc2[i][0]), p1 = unpack2(acc2[i][1]);
        float2 p2 = unpack2(acc2[i][2]), p3 = unpack2(acc2[i][3]);
        float4 o0, o1;
        o0.x = p0.x + bb0.x; o0.y = p0.y + bb0.y;
        o0.z = p1.x + bb0.z; o0.w = p1.y + bb0.w;
        o1.x = p2.x + bb1.x; o1.y = p2.y + bb1.y;
        o1.z = p3.x + bb1.z; o1.w = p3.y + bb1.w;
        *(float4*)(g_h + (size_t)(crow + i) * NO + ccol) = o0;
        *(float4*)(g_h + (size_t)(crow + i) * NO + ccol + 4) = o1;
    }
}

// ===================== xnorm (hn = 0.5|x|^2) =================================
__global__ __launch_bounds__(128) void xnorm_kernel(const float* __restrict__ feat) {
    int row = blockIdx.x * 4 + (threadIdx.x >> 5);
    int lane = threadIdx.x & 31;
    const float* f = feat + (size_t)row * NF;
    float s = 0.f;
#pragma unroll
    for (int i = 0; i < NF / 32; i++) {
        float v = f[lane + 32 * i];
        s = fmaf(v, v, s);
    }
#pragma unroll
    for (int off = 16; off > 0; off >>= 1) s += __shfl_down_sync(0xffffffffu, s, off);
    if (lane == 0) g_hn[row] = 0.5f * s;
}

// ===================== int8 quantization (1 warp per point) ==================
__global__ __launch_bounds__(256) void quant_kernel(const float* __restrict__ feat) {
    const int pt = blockIdx.x * 8 + (threadIdx.x >> 5);
    const int lane = threadIdx.x & 31;
    const float* f = feat + (size_t)pt * NF + lane * 8;
    float4 v0 = *(const float4*)f;
    float4 v1 = *(const float4*)(f + 4);
    float m = fmaxf(fmaxf(fmaxf(fabsf(v0.x), fabsf(v0.y)), fmaxf(fabsf(v0.z), fabsf(v0.w))),
                    fmaxf(fmaxf(fabsf(v1.x), fabsf(v1.y)), fmaxf(fabsf(v1.z), fabsf(v1.w))));
#pragma unroll
    for (int off = 16; off > 0; off >>= 1)
        m = fmaxf(m, __shfl_xor_sync(0xffffffffu, m, off));
    m = fmaxf(m, 1e-30f);
    float inv = 127.0f / m;
    int q[8];
    const float* vv0 = &v0.x;
    const float* vv1 = &v1.x;
#pragma unroll
    for (int j = 0; j < 4; j++) {
        q[j]     = max(-127, min(127, __float2int_rn(vv0[j] * inv)));
        q[j + 4] = max(-127, min(127, __float2int_rn(vv1[j] * inv)));
    }
    uint32_t p0 = (q[0] & 255) | ((q[1] & 255) << 8) | ((q[2] & 255) << 16) | ((uint32_t)(q[3] & 255) << 24);
    uint32_t p1 = (q[4] & 255) | ((q[5] & 255) << 8) | ((q[6] & 255) << 16) | ((uint32_t)(q[7] & 255) << 24);
    g_q8[(size_t)pt * 64 + lane * 2]     = p0;
    g_q8[(size_t)pt * 64 + lane * 2 + 1] = p1;
    if (lane == 0) g_qs[pt] = m * (1.0f / 127.0f);
}

// ===================== BN stats =====================
__global__ __launch_bounds__(512) void stats_partial_kernel() {
    int c = threadIdx.x, blk = blockIdx.x;
    float s = 0.f, s2 = 0.f;
    int r0 = blk * 512;
    for (int r = 0; r < 512; r++) {
        float v = g_h[(size_t)(r0 + r) * NO + c];
        s += v; s2 = fmaf(v, v, s2);
    }
    g_part[blk * NO + c] = s;
    g_part[128 * NO + blk * NO + c] = s2;
}
__global__ __launch_bounds__(512) void stats_final_kernel(const float* __restrict__ gamma,
                                                          const float* __restrict__ beta) {
    int c = threadIdx.x;
    float s = 0.f, s2 = 0.f;
    for (int b = 0; b < 128; b++) { s += g_part[b * NO + c]; s2 += g_part[128 * NO + b * NO + c]; }
    float inv = 1.0f / (float)NPTS;
    float mu = s * inv, var = s2 * inv - mu * mu;
    float a = gamma[c] * rsqrtf(var + 1e-5f);
    g_a[c] = a; g_c[c] = beta[c] - mu * a;
}

// ===================== KNN int8 (SEG=2, 256 blocks = one occ-2 wave) =========
#define I_Q  0                              // 64 u32-k x 128 rows = 32768
#define I_X  (I_Q + 32768)                  // 2 x (16 k x 512B) = 16384
#define I_SC (I_X + 16384)                  // 128 x 65 int = 33280
#define I_SX (I_SC + 33280)
#define I_HN (I_SX + 512)
#define I_TV (I_HN + 512)
#define I_TI (I_TV + 128*NKC*4)
#define KNN8_SMEM (I_TI + 128*NKC*4)        // 108032 -> 2 blocks/SM

__global__ __launch_bounds__(256, 2) void knn_i8_kernel() {
    extern __shared__ __align__(16) char smc[];
    uint32_t* Qs  = (uint32_t*)(smc + I_Q);
    char*  Xm   = smc + I_X;
    int*   Sc   = (int*)(smc + I_SC);
    float* sx_s = (float*)(smc + I_SX);
    float* hn_s = (float*)(smc + I_HN);
    float* topv = (float*)(smc + I_TV);
    int*   topi = (int*)(smc + I_TI);

    const int qt = blockIdx.x, sg = blockIdx.y, cloud = blockIdx.z;
    const int tid = threadIdx.x;
    const int tx = tid & 15, ty = tid >> 4;
    const int qbase = cloud * NS + qt * 128;

    for (int i = tid; i < 2048; i += 256) {
        int row = i & 127, kg = i >> 7;
        int qr = g_fps[qbase + row];
        uint4 v = ((const uint4*)(g_q8 + (size_t)qr * 64))[kg];
        Qs[(kg * 4 + 0) * 128 + row] = v.x;
        Qs[(kg * 4 + 1) * 128 + row] = v.y;
        Qs[(kg * 4 + 2) * 128 + row] = v.z;
        Qs[(kg * 4 + 3) * 128 + row] = v.w;
    }
    if (tid < 128) {
#pragma unroll
        for (int r = 0; r < NKC; r++) {
            topv[tid * NKC + r] = NEG_INF;
            topi[tid * NKC + r] = 0x7fffffff;
        }
    }
    float sq_t = (tid < 128) ? g_qs[g_fps[qbase + tid]] : 0.f;
    const int xcloudbase = cloud * NP + sg * PSEG;

    const int lr0 = tid & 127, lg0 = tid >> 7;
    const int lg1 = lg0 + 2;
    const int xo = xoff(lr0);
    __syncthreads();

    for (int t = 0; t < PSEG / 128; t++) {
        const int xbase = xcloudbase + t * 128;
        if (tid < 128) {
            sx_s[tid] = g_qs[xbase + tid];
            hn_s[tid] = g_hn[xbase + tid];
        }

        int acc[8][8];
#pragma unroll
        for (int i = 0; i < 8; i++)
#pragma unroll
            for (int j = 0; j < 8; j++) acc[i][j] = 0;

        uint4 xv0 = ((const uint4*)(g_q8 + (size_t)(xbase + lr0) * 64))[lg0];
        uint4 xv1 = ((const uint4*)(g_q8 + (size_t)(xbase + lr0) * 64))[lg1];

        for (int c = 0; c < 4; c++) {
            char* Xb = Xm + (c & 1) * 8192;
            {
                char* r0 = Xb + (lg0 * 4) * 512 + xo;
                *(uint32_t*)(r0)         = xv0.x;
                *(uint32_t*)(r0 + 512)   = xv0.y;
                *(uint32_t*)(r0 + 1024)  = xv0.z;
                *(uint32_t*)(r0 + 1536)  = xv0.w;
                char* r1 = Xb + (lg1 * 4) * 512 + xo;
                *(uint32_t*)(r1)         = xv1.x;
                *(uint32_t*)(r1 + 512)   = xv1.y;
                *(uint32_t*)(r1 + 1024)  = xv1.z;
                *(uint32_t*)(r1 + 1536)  = xv1.w;
            }
            __syncthreads();
            if (c < 3) {
                xv0 = ((const uint4*)(g_q8 + (size_t)(xbase + lr0) * 64))[(c + 1) * 4 + lg0];
                xv1 = ((const uint4*)(g_q8 + (size_t)(xbase + lr0) * 64))[(c + 1) * 4 + lg1];
            }
            const uint32_t* Qc = Qs + c * 16 * 128;
#pragma unroll 4
            for (int kk = 0; kk < 16; kk++) {
                uint4 a0 = *(const uint4*)&Qc[kk * 128 + ty * 8];
                uint4 a1 = *(const uint4*)&Qc[kk * 128 + ty * 8 + 4];
                const char* xrow = Xb + kk * 512;
                uint2 bq0 = *(const uint2*)(xrow + (0 * 16 + tx) * 8);
                uint2 bq1 = *(const uint2*)(xrow + (1 * 16 + tx) * 8);
                uint2 bq2 = *(const uint2*)(xrow + (2 * 16 + tx) * 8);
                uint2 bq3 = *(const uint2*)(xrow + (3 * 16 + tx) * 8);
                int ar[8] = {(int)a0.x, (int)a0.y, (int)a0.z, (int)a0.w,
                             (int)a1.x, (int)a1.y, (int)a1.z, (int)a1.w};
                int br[8] = {(int)bq0.x, (int)bq0.y, (int)bq1.x, (int)bq1.y,
                             (int)bq2.x, (int)bq2.y, (int)bq3.x, (int)bq3.y};
#pragma unroll
                for (int i = 0; i < 8; i++)
#pragma unroll
                    for (int j = 0; j < 8; j++)
                        acc[i][j] = __dp4a(ar[i], br[j], acc[i][j]);
            }
        }
        __syncthreads();

#pragma unroll
        for (int half = 0; half < 2; half++) {
            if ((tx >> 3) == half) {
                int cx = (tx & 7) * 8;
#pragma unroll
                for (int i = 0; i < 8; i++)
#pragma unroll
                    for (int j = 0; j < 8; j++)
                        Sc[(ty * 8 + i) * 65 + cx + j] = acc[i][j];
            }
            __syncthreads();
            if (tid < 128) {
                const int* scr = Sc + tid * 65;
                float* tv = topv + tid * NKC;
                int*   ti = topi + tid * NKC;
                float th = tv[NKC - 1];
                int  thi = ti[NKC - 1];
                const int pb = half * 64;
                for (int p = 0; p < 64; p++) {
                    float s = sq_t * sx_s[pb + p] * (float)scr[p] - hn_s[pb + p];
                    int gi = xbase + pb + p;
                    if (s > th || (s == th && gi < thi)) {
                        int r = NKC - 1;
                        while (r > 0) {
                            float pv = tv[r - 1];
                            int   pi = ti[r - 1];
                            if (s > pv || (s == pv && gi < pi)) {
                                tv[r] = pv; ti[r] = pi; r--;
                            } else break;
                        }
                        tv[r] = s; ti[r] = gi;
                        th = tv[NKC - 1]; thi = ti[NKC - 1];
                    }
                }
            }
            __syncthreads();
        }
    }

    if (tid < 128) {
        int q = qbase + tid;
#pragma unroll
        for (int r = 0; r < NKC; r++)
            g_knni[(size_t)q * NCAND + sg * NKC + r] = topi[tid * NKC + r];
    }
}

// ===================== fused exact rescore (48 cand) + gather ================
// Rescore reproduces round-1 arithmetic bit-exactly: ascending-k fmaf dot,
// s -= 0.5|x|^2, rank by (score desc, index asc) -> top-16 -> gather+BN+ReLU.
__global__ __launch_bounds__(128) void rescore_gather_kernel(const float* __restrict__ feat,
                                                             float* __restrict__ out) {
    __shared__ float q[NF];
    __shared__ float sv[NCAND];
    __shared__ int   si[NCAND];
    __shared__ int   nn[NK];
    const int qi = blockIdx.x, tid = threadIdx.x;
    const int qg = g_fps[qi];
    q[tid]       = feat[(size_t)qg * NF + tid];
    q[tid + 128] = feat[(size_t)qg * NF + 128 + tid];
    __syncthreads();

    if (tid < NCAND) {
        int gi = g_knni[(size_t)qi * NCAND + tid];
        const float4* x = (const float4*)(feat + (size_t)gi * NF);
        float s = 0.f;
#pragma unroll 8
        for (int k4 = 0; k4 < NF / 4; k4++) {
            float4 xv = x[k4];
            s = fmaf(q[k4 * 4 + 0], xv.x, s);
            s = fmaf(q[k4 * 4 + 1], xv.y, s);
            s = fmaf(q[k4 * 4 + 2], xv.z, s);
            s = fmaf(q[k4 * 4 + 3], xv.w, s);
        }
        s -= g_hn[gi];
        sv[tid] = s;
        si[tid] = gi;
    }
    __syncthreads();

    if (tid < NCAND) {
        float s = sv[tid];
        int gi = si[tid];
        int cnt = 0;
        for (int j = 0; j < NCAND; j++) {
            float vj = sv[j];
            cnt += (vj > s || (vj == s && si[j] < gi)) ? 1 : 0;
        }
        if (cnt < NK) nn[cnt] = gi;
    }
    __syncthreads();

    float mx[4] = {NEG_INF, NEG_INF, NEG_INF, NEG_INF};
    float mn[4] = {POS_INF, POS_INF, POS_INF, POS_INF};
#pragma unroll
    for (int n = 0; n < NK; n++) {
        const float* hp = g_h + (size_t)nn[n] * NO;
#pragma unroll
        for (int j = 0; j < 4; j++) {
            float v = hp[tid + j * 128];
            mx[j] = fmaxf(mx[j], v); mn[j] = fminf(mn[j], v);
        }
    }
    float* op = out + (size_t)qi * NO;
#pragma unroll
    for (int j = 0; j < 4; j++) {
        int c = tid + j * 128;
        float a = g_a[c], cc = g_c[c];
        float o = fmaxf(fmaf(a, mx[j], cc), fmaf(a, mn[j], cc));
        op[c] = fmaxf(o, 0.0f);
    }
}

// ===================== launch =====================
extern "C" void kernel_launch(void* const* d_in, const int* in_sizes, int n_in,
                              void* d_out, int out_size) {
    (void)in_sizes; (void)n_in; (void)out_size;
    const float* features  = (const float*)d_in[0];
    const float* positions = (const float*)d_in[1];
    const int*   batch     = (const int*)d_in[2];
    const float* W         = (const float*)d_in[3];
    const float* bias      = (const float*)d_in[4];
    const float* gamma     = (const float*)d_in[5];
    const float* beta      = (const float*)d_in[6];

    float* out       = (float*)d_out;
    float* out_feat  = out;
    float* out_pos   = out + (size_t)NQ * NO;
    float* out_batch = out_pos + (size_t)NQ * 3;

    cudaFuncSetAttribute(fused_kernel, cudaFuncAttributeMaxDynamicSharedMemorySize, FUSED_SMEM);
    cudaFuncSetAttribute(knn_i8_kernel, cudaFuncAttributeMaxDynamicSharedMemorySize, KNN8_SMEM);

    quant_kernel<<<NPTS / 8, 256>>>(features);
    xnorm_kernel<<<NPTS / 4, 128>>>(features);
    fused_kernel<<<16 + 2048, 256, FUSED_SMEM>>>(features, positions, batch, W, bias,
                                                 out_pos, out_batch);
    knn_i8_kernel<<<dim3(8, SEG, NB), 256, KNN8_SMEM>>>();   // 4th launch -> ncu
    stats_partial_kernel<<<128, 512>>>();
    stats_final_kernel<<<1, 512>>>(gamma, beta);
    rescore_gather_kernel<<<NQ, 128>>>(features, out_feat);
}